// round 1
// baseline (speedup 1.0000x reference)
#include <cuda_runtime.h>
#include <math.h>

#define BATCH 2
#define SEQ   2048
#define DIN   2048
#define DOUT  2048
#define NH    32
#define NKV   8
#define HD    64
#define ROWS  (BATCH*SEQ)    /* 4096 */
#define DKV   (NKV*HD)       /* 512  */

// ---------------- scratch (static device arrays; no allocation) ----------------
__device__ float g_Q  [ROWS*DOUT];
__device__ float g_K  [ROWS*DKV];
__device__ float g_V  [ROWS*DKV];
__device__ float g_Qr [ROWS*DOUT];   // [B,NH,S,HD]
__device__ float g_Kr [ROWS*DKV];    // [B,NKV,S,HD]
__device__ float g_Vr [ROWS*DKV];    // [B,NKV,S,HD]
__device__ float g_ctx[ROWS*DOUT];   // [B*S, NH*HD]

// ---------------- SGEMM: C[M,N] = A[M,K] @ B[K,N], fp32, row-major -------------
// 128x128 block, 16 k-tile, 256 threads, 8x8 per-thread microtile.
__global__ __launch_bounds__(256) void sgemm_k(
    const float* __restrict__ A, const float* __restrict__ B,
    float* __restrict__ C, int M, int N, int K)
{
    __shared__ float As[16][132];   // transposed, +4 pad (keeps 16B alignment)
    __shared__ float Bs[16][128];

    const int tid = threadIdx.x;
    const int tx  = tid & 15, ty = tid >> 4;
    const int row0 = blockIdx.y * 128, col0 = blockIdx.x * 128;

    const int arow = tid >> 2,  acol = (tid & 3) << 2;   // A: 2 rows x float4
    const int brow = tid >> 5,  bcol = (tid & 31) << 2;  // B: 2 rows x float4

    const float* Aptr = A + (size_t)(row0 + arow) * K + acol;
    const float* Bptr = B + (size_t)brow * N + col0 + bcol;

    float acc[8][8];
    #pragma unroll
    for (int i = 0; i < 8; i++)
        #pragma unroll
        for (int j = 0; j < 8; j++) acc[i][j] = 0.f;

    for (int k0 = 0; k0 < K; k0 += 16) {
        float4 a0 = *(const float4*)(Aptr + k0);
        float4 a1 = *(const float4*)(Aptr + (size_t)64 * K + k0);
        float4 b0 = *(const float4*)(Bptr + (size_t)k0 * N);
        float4 b1 = *(const float4*)(Bptr + (size_t)(k0 + 8) * N);

        As[acol+0][arow]    = a0.x; As[acol+1][arow]    = a0.y;
        As[acol+2][arow]    = a0.z; As[acol+3][arow]    = a0.w;
        As[acol+0][arow+64] = a1.x; As[acol+1][arow+64] = a1.y;
        As[acol+2][arow+64] = a1.z; As[acol+3][arow+64] = a1.w;
        *(float4*)&Bs[brow  ][bcol] = b0;
        *(float4*)&Bs[brow+8][bcol] = b1;
        __syncthreads();

        #pragma unroll 8
        for (int kk = 0; kk < 16; kk++) {
            float a[8], bb[8];
            *(float4*)&a[0]  = *(const float4*)&As[kk][ty*8];
            *(float4*)&a[4]  = *(const float4*)&As[kk][ty*8 + 4];
            *(float4*)&bb[0] = *(const float4*)&Bs[kk][tx*8];
            *(float4*)&bb[4] = *(const float4*)&Bs[kk][tx*8 + 4];
            #pragma unroll
            for (int i = 0; i < 8; i++)
                #pragma unroll
                for (int j = 0; j < 8; j++)
                    acc[i][j] = fmaf(a[i], bb[j], acc[i][j]);
        }
        __syncthreads();
    }

    #pragma unroll
    for (int i = 0; i < 8; i++) {
        float* cp = C + (size_t)(row0 + ty*8 + i) * N + col0 + tx*8;
        *(float4*)(cp    ) = make_float4(acc[i][0], acc[i][1], acc[i][2], acc[i][3]);
        *(float4*)(cp + 4) = make_float4(acc[i][4], acc[i][5], acc[i][6], acc[i][7]);
    }
}

// ---------------- RoPE + [B*S, H*64] -> [B,H,S,64] transpose -------------------
__global__ void rope_k(const float* __restrict__ in, const float* __restrict__ cosb,
                       const float* __restrict__ sinb, float* __restrict__ out, int nheads)
{
    int idx = blockIdx.x * blockDim.x + threadIdx.x;   // (row, h, d<32)
    int d = idx & 31;
    int h = (idx >> 5) % nheads;
    int row = idx / (nheads * 32);
    int b = row >> 11, s = row & 2047;

    const float* ip = in + (size_t)row * (nheads * HD) + h * HD;
    float x1 = ip[d], x2 = ip[d + 32];
    float c1 = cosb[s * HD + d],      s1 = sinb[s * HD + d];
    float c2 = cosb[s * HD + d + 32], s2 = sinb[s * HD + d + 32];

    float* op = out + ((size_t)(b * nheads + h) * SEQ + s) * HD;
    op[d]      = x1 * c1 - x2 * s1;
    op[d + 32] = x2 * c2 + x1 * s2;
}

// ---------------- V transpose [B*S, G*64] -> [B,G,S,64] (float4) --------------
__global__ void vtrans_k(const float* __restrict__ in, float* __restrict__ out)
{
    int idx = blockIdx.x * blockDim.x + threadIdx.x;   // float4 index
    int d4  = idx & 15;
    int g   = (idx >> 4) & 7;
    int row = idx >> 7;
    int b = row >> 11, s = row & 2047;
    float4 v = ((const float4*)in)[idx];
    ((float4*)out)[((size_t)(b * NKV + g) * SEQ + s) * 16 + d4] = v;
}

// ---------------- Flash attention: 128-q x 64-k tiles, causal -----------------
// smem: Qt[64][128] (d-major), Kt[64][64] (d-major), Vs[64][64], P[128][64]
#define ATTN_SMEM ((64*128 + 64*64 + 64*64 + 128*64) * 4)

__global__ __launch_bounds__(256) void attn_k(
    const float* __restrict__ Qr, const float* __restrict__ Kr,
    const float* __restrict__ Vr, float* __restrict__ ctx)
{
    extern __shared__ float sm[];
    float* Qt = sm;                 // [64][128]
    float* Kt = Qt + 64 * 128;      // [64][64]
    float* Vs = Kt + 64 * 64;       // [64][64]
    float* P  = Vs + 64 * 64;       // [128][64]

    const int bh = blockIdx.y;                 // b*32 + h
    const int b = bh >> 5, h = bh & 31, g = h >> 2;
    const int q0 = blockIdx.x * 128;
    const int tid = threadIdx.x;
    const int tx = tid & 15, ty = tid >> 4;    // 16 x 16 thread grid

    const float* Qbase = Qr + ((size_t)bh * SEQ + q0) * HD;
    const float* Kbase = Kr + (size_t)(b * NKV + g) * SEQ * HD;
    const float* Vbase = Vr + (size_t)(b * NKV + g) * SEQ * HD;

    // load Q tile transposed: Qt[d][q]
    {
        int q = tid & 127, half = tid >> 7;
        const float* qp = Qbase + q * HD + half * 32;
        #pragma unroll
        for (int i = 0; i < 8; i++) {
            float4 v = *(const float4*)(qp + i * 4);
            int d = half * 32 + i * 4;
            Qt[(d+0)*128 + q] = v.x; Qt[(d+1)*128 + q] = v.y;
            Qt[(d+2)*128 + q] = v.z; Qt[(d+3)*128 + q] = v.w;
        }
    }

    float m_[8], l_[8], acc[8][4];
    #pragma unroll
    for (int i = 0; i < 8; i++) {
        m_[i] = -1e30f; l_[i] = 0.f;
        #pragma unroll
        for (int j = 0; j < 4; j++) acc[i][j] = 0.f;
    }

    const int ntiles = q0 / 64 + 2;
    for (int t = 0; t < ntiles; t++) {
        const int k0 = t * 64;
        __syncthreads();
        // load K tile transposed Kt[d][k], V tile straight Vs[k][d]
        {
            int k = tid & 63, part = tid >> 6;
            const float* kp = Kbase + (size_t)(k0 + k) * HD + part * 16;
            #pragma unroll
            for (int i = 0; i < 4; i++) {
                float4 v = *(const float4*)(kp + i * 4);
                int d = part * 16 + i * 4;
                Kt[(d+0)*64 + k] = v.x; Kt[(d+1)*64 + k] = v.y;
                Kt[(d+2)*64 + k] = v.z; Kt[(d+3)*64 + k] = v.w;
            }
            const float4* vp = (const float4*)(Vbase + (size_t)k0 * HD);
            float4* vsp = (float4*)Vs;
            #pragma unroll
            for (int i = 0; i < 4; i++) vsp[tid + i * 256] = vp[tid + i * 256];
        }
        __syncthreads();

        // scores S[q][k] = Q·K^T  (8x4 per-thread tile)
        float s[8][4];
        #pragma unroll
        for (int i = 0; i < 8; i++)
            #pragma unroll
            for (int j = 0; j < 4; j++) s[i][j] = 0.f;

        #pragma unroll 8
        for (int d = 0; d < 64; d++) {
            float a[8], bb[4];
            *(float4*)&a[0]  = *(const float4*)&Qt[d*128 + ty*8];
            *(float4*)&a[4]  = *(const float4*)&Qt[d*128 + ty*8 + 4];
            *(float4*)&bb[0] = *(const float4*)&Kt[d*64 + tx*4];
            #pragma unroll
            for (int i = 0; i < 8; i++)
                #pragma unroll
                for (int j = 0; j < 4; j++)
                    s[i][j] = fmaf(a[i], bb[j], s[i][j]);
        }

        // scale + causal mask (only last two tiles can touch the diagonal)
        const bool do_mask = (k0 + 63 > q0);
        #pragma unroll
        for (int i = 0; i < 8; i++) {
            const int qg = q0 + ty*8 + i;
            #pragma unroll
            for (int j = 0; j < 4; j++) {
                float v = s[i][j] * 0.125f;           // 1/sqrt(64)
                if (do_mask && (k0 + tx*4 + j > qg)) v = -1e30f;
                s[i][j] = v;
            }
        }

        // online softmax: row reductions across the 16 tx lanes (xor<16 stays in group)
        #pragma unroll
        for (int i = 0; i < 8; i++) {
            float tm = fmaxf(fmaxf(s[i][0], s[i][1]), fmaxf(s[i][2], s[i][3]));
            tm = fmaxf(tm, __shfl_xor_sync(0xffffffffu, tm, 1));
            tm = fmaxf(tm, __shfl_xor_sync(0xffffffffu, tm, 2));
            tm = fmaxf(tm, __shfl_xor_sync(0xffffffffu, tm, 4));
            tm = fmaxf(tm, __shfl_xor_sync(0xffffffffu, tm, 8));
            float mn = fmaxf(m_[i], tm);
            float alpha = __expf(m_[i] - mn);
            m_[i] = mn;
            float rs = 0.f;
            #pragma unroll
            for (int j = 0; j < 4; j++) {
                float p = __expf(s[i][j] - mn);
                s[i][j] = p; rs += p;
            }
            rs += __shfl_xor_sync(0xffffffffu, rs, 1);
            rs += __shfl_xor_sync(0xffffffffu, rs, 2);
            rs += __shfl_xor_sync(0xffffffffu, rs, 4);
            rs += __shfl_xor_sync(0xffffffffu, rs, 8);
            l_[i] = l_[i] * alpha + rs;
            #pragma unroll
            for (int j = 0; j < 4; j++) acc[i][j] *= alpha;
            *(float4*)&P[(ty*8 + i)*64 + tx*4] =
                make_float4(s[i][0], s[i][1], s[i][2], s[i][3]);
        }
        __syncwarp();   // P rows are produced/consumed within the same warp

        // O += P @ V
        #pragma unroll 4
        for (int k = 0; k < 64; k++) {
            float4 v4 = *(const float4*)&Vs[k*64 + tx*4];
            #pragma unroll
            for (int i = 0; i < 8; i++) {
                float p = P[(ty*8 + i)*64 + k];   // broadcast
                acc[i][0] = fmaf(p, v4.x, acc[i][0]);
                acc[i][1] = fmaf(p, v4.y, acc[i][1]);
                acc[i][2] = fmaf(p, v4.z, acc[i][2]);
                acc[i][3] = fmaf(p, v4.w, acc[i][3]);
            }
        }
    }

    // epilogue: write context as [B*S, NH*HD]
    #pragma unroll
    for (int i = 0; i < 8; i++) {
        float inv = 1.f / l_[i];
        int qg = q0 + ty*8 + i;
        float* cp = ctx + ((size_t)(b * SEQ + qg)) * DOUT + h * HD + tx*4;
        *(float4*)cp = make_float4(acc[i][0]*inv, acc[i][1]*inv,
                                   acc[i][2]*inv, acc[i][3]*inv);
    }
}

// ------------------------------- launcher -------------------------------------
extern "C" void kernel_launch(void* const* d_in, const int* in_sizes, int n_in,
                              void* d_out, int out_size)
{
    const float* x    = (const float*)d_in[0];
    const float* Wq   = (const float*)d_in[1];
    const float* Wk   = (const float*)d_in[2];
    const float* Wv   = (const float*)d_in[3];
    const float* Wo   = (const float*)d_in[4];
    const float* cosb = (const float*)d_in[5];
    const float* sinb = (const float*)d_in[6];
    float* out = (float*)d_out;

    float *pQ, *pK, *pV, *pQr, *pKr, *pVr, *pCtx;
    cudaGetSymbolAddress((void**)&pQ,   g_Q);
    cudaGetSymbolAddress((void**)&pK,   g_K);
    cudaGetSymbolAddress((void**)&pV,   g_V);
    cudaGetSymbolAddress((void**)&pQr,  g_Qr);
    cudaGetSymbolAddress((void**)&pKr,  g_Kr);
    cudaGetSymbolAddress((void**)&pVr,  g_Vr);
    cudaGetSymbolAddress((void**)&pCtx, g_ctx);

    dim3 thr(256);

    // QKV projections
    sgemm_k<<<dim3(DOUT/128, ROWS/128), thr>>>(x, Wq, pQ, ROWS, DOUT, DIN);
    sgemm_k<<<dim3(DKV /128, ROWS/128), thr>>>(x, Wk, pK, ROWS, DKV, DIN);
    sgemm_k<<<dim3(DKV /128, ROWS/128), thr>>>(x, Wv, pV, ROWS, DKV, DIN);

    // RoPE + head-major transposes
    rope_k<<<(ROWS * NH  * 32) / 256, thr>>>(pQ, cosb, sinb, pQr, NH);
    rope_k<<<(ROWS * NKV * 32) / 256, thr>>>(pK, cosb, sinb, pKr, NKV);
    vtrans_k<<<(ROWS * DKV / 4) / 256, thr>>>(pV, pVr);

    // causal flash attention
    cudaFuncSetAttribute(attn_k, cudaFuncAttributeMaxDynamicSharedMemorySize, ATTN_SMEM);
    attn_k<<<dim3(SEQ/128, BATCH*NH), thr, ATTN_SMEM>>>(pQr, pKr, pVr, pCtx);

    // output projection
    sgemm_k<<<dim3(DOUT/128, ROWS/128), thr>>>(pCtx, Wo, out, ROWS, DOUT, DIN);
}

// round 2
// speedup vs baseline: 1.4729x; 1.4729x over previous
#include <cuda_runtime.h>
#include <math.h>
#include <stdint.h>

#define BATCH 2
#define SEQ   2048
#define DIN   2048
#define DOUT  2048
#define NH    32
#define NKV   8
#define HD    64
#define ROWS  (BATCH*SEQ)    /* 4096 */
#define DKV   (NKV*HD)       /* 512  */

// ---------------- scratch (static device arrays; no allocation) ----------------
__device__ float g_Q  [ROWS*DOUT];
__device__ float g_K  [ROWS*DKV];
__device__ float g_V  [ROWS*DKV];
__device__ float g_Qr [ROWS*DOUT];   // [B,NH,S,HD]
__device__ float g_Kr [ROWS*DKV];    // [B,NKV,S,HD]
__device__ float g_Vr [ROWS*DKV];    // [B,NKV,S,HD]
__device__ float g_ctx[ROWS*DOUT];   // [B*S, NH*HD]

// ---------------- tf32 tensor-core GEMM ----------------------------------------
// C[M,N] = A[M,K] @ B[K,N], row-major fp32 in/out, tf32 MMA, fp32 accum.
// 128x128x32 block tile, 256 threads = 8 warps in 4x2 grid of 32x64 warp tiles.
// smem k-major with stride 136 (mod 32 == 8 -> conflict-free fragment loads).
// Double-buffered smem + register-staged global loads.

__device__ __forceinline__ uint32_t f2tf(float f) {
    uint32_t r;
    asm("cvt.rna.tf32.f32 %0, %1;" : "=r"(r) : "f"(f));
    return r;
}

#define TCK      32
#define TSTRIDE  136
#define SGEMM_SMEM (2 * TCK * TSTRIDE * 2 * 4)   /* 69632 bytes */

__global__ __launch_bounds__(256) void sgemm_tc(
    const float* __restrict__ A, const float* __restrict__ B,
    float* __restrict__ C, int M, int N, int K)
{
    extern __shared__ uint32_t sm_u[];
    uint32_t* As = sm_u;                         // [2][32][136]
    uint32_t* Bs = sm_u + 2 * TCK * TSTRIDE;     // [2][32][136]

    const int tid  = threadIdx.x;
    const int warp = tid >> 5, lane = tid & 31;
    const int g    = lane >> 2, t = lane & 3;
    const int wm   = (warp & 3) * 32;            // warp row offset
    const int wn   = (warp >> 2) * 64;           // warp col offset
    const int row0 = blockIdx.y * 128, col0 = blockIdx.x * 128;

    const int ar = tid >> 1, ac = (tid & 1) * 16;   // A: 1 row x 16 k per thread
    const int br = tid >> 3, bc = (tid & 7) * 16;   // B: 1 k-row x 16 n per thread

    const float* Ap = A + (size_t)(row0 + ar) * K + ac;
    const float* Bp = B + (size_t)br * N + col0 + bc;

    float acc[2][8][4];
    #pragma unroll
    for (int mi = 0; mi < 2; mi++)
        #pragma unroll
        for (int ni = 0; ni < 8; ni++)
            #pragma unroll
            for (int r = 0; r < 4; r++) acc[mi][ni][r] = 0.f;

    float4 av[4], bv[4];

    // ---- stage tile k0 from global into registers
    auto LOADG = [&](int k0) {
        #pragma unroll
        for (int i = 0; i < 4; i++) av[i] = *(const float4*)(Ap + k0 + i * 4);
        #pragma unroll
        for (int i = 0; i < 4; i++) bv[i] = *(const float4*)(Bp + (size_t)k0 * N + i * 4);
    };

    // ---- convert + store staged tile into smem buffer
    auto STORE = [&](int buf) {
        #pragma unroll
        for (int i = 0; i < 4; i++) {
            const int k = ac + i * 4;
            As[(buf * TCK + k + 0) * TSTRIDE + ar] = f2tf(av[i].x);
            As[(buf * TCK + k + 1) * TSTRIDE + ar] = f2tf(av[i].y);
            As[(buf * TCK + k + 2) * TSTRIDE + ar] = f2tf(av[i].z);
            As[(buf * TCK + k + 3) * TSTRIDE + ar] = f2tf(av[i].w);
        }
        #pragma unroll
        for (int i = 0; i < 4; i++) {
            uint4 w;
            w.x = f2tf(bv[i].x); w.y = f2tf(bv[i].y);
            w.z = f2tf(bv[i].z); w.w = f2tf(bv[i].w);
            *(uint4*)&Bs[(buf * TCK + br) * TSTRIDE + bc + i * 4] = w;
        }
    };

    // ---- one 128x128x32 MMA pass over smem buffer
    auto MMASTEP = [&](int buf) {
        #pragma unroll
        for (int ks = 0; ks < 4; ks++) {
            const int kb = buf * TCK + ks * 8;
            uint32_t a[2][4], b[8][2];
            #pragma unroll
            for (int mi = 0; mi < 2; mi++) {
                const int m0 = wm + mi * 16 + g;
                a[mi][0] = As[(kb + t    ) * TSTRIDE + m0];
                a[mi][1] = As[(kb + t    ) * TSTRIDE + m0 + 8];
                a[mi][2] = As[(kb + t + 4) * TSTRIDE + m0];
                a[mi][3] = As[(kb + t + 4) * TSTRIDE + m0 + 8];
            }
            #pragma unroll
            for (int ni = 0; ni < 8; ni++) {
                const int n0 = wn + ni * 8 + g;
                b[ni][0] = Bs[(kb + t    ) * TSTRIDE + n0];
                b[ni][1] = Bs[(kb + t + 4) * TSTRIDE + n0];
            }
            #pragma unroll
            for (int mi = 0; mi < 2; mi++)
                #pragma unroll
                for (int ni = 0; ni < 8; ni++) {
                    float* c = acc[mi][ni];
                    asm volatile(
                        "mma.sync.aligned.m16n8k8.row.col.f32.tf32.tf32.f32 "
                        "{%0,%1,%2,%3}, {%4,%5,%6,%7}, {%8,%9}, {%0,%1,%2,%3};"
                        : "+f"(c[0]), "+f"(c[1]), "+f"(c[2]), "+f"(c[3])
                        : "r"(a[mi][0]), "r"(a[mi][1]), "r"(a[mi][2]), "r"(a[mi][3]),
                          "r"(b[ni][0]), "r"(b[ni][1]));
                }
        }
    };

    LOADG(0);
    STORE(0);
    __syncthreads();

    const int niter = K / TCK;
    for (int it = 0; it < niter; it++) {
        const int buf = it & 1;
        if (it + 1 < niter) LOADG((it + 1) * TCK);
        MMASTEP(buf);
        if (it + 1 < niter) STORE(buf ^ 1);
        __syncthreads();
    }

    #pragma unroll
    for (int mi = 0; mi < 2; mi++)
        #pragma unroll
        for (int ni = 0; ni < 8; ni++) {
            const int r = row0 + wm + mi * 16 + g;
            const int c = col0 + wn + ni * 8 + t * 2;
            *(float2*)(C + (size_t)r * N + c) =
                make_float2(acc[mi][ni][0], acc[mi][ni][1]);
            *(float2*)(C + (size_t)(r + 8) * N + c) =
                make_float2(acc[mi][ni][2], acc[mi][ni][3]);
        }
}

// ---------------- RoPE + [B*S, H*64] -> [B,H,S,64] transpose -------------------
__global__ void rope_k(const float* __restrict__ in, const float* __restrict__ cosb,
                       const float* __restrict__ sinb, float* __restrict__ out, int nheads)
{
    int idx = blockIdx.x * blockDim.x + threadIdx.x;   // (row, h, d<32)
    int d = idx & 31;
    int h = (idx >> 5) % nheads;
    int row = idx / (nheads * 32);
    int b = row >> 11, s = row & 2047;

    const float* ip = in + (size_t)row * (nheads * HD) + h * HD;
    float x1 = ip[d], x2 = ip[d + 32];
    float c1 = cosb[s * HD + d],      s1 = sinb[s * HD + d];
    float c2 = cosb[s * HD + d + 32], s2 = sinb[s * HD + d + 32];

    float* op = out + ((size_t)(b * nheads + h) * SEQ + s) * HD;
    op[d]      = x1 * c1 - x2 * s1;
    op[d + 32] = x2 * c2 + x1 * s2;
}

// ---------------- V transpose [B*S, G*64] -> [B,G,S,64] (float4) --------------
__global__ void vtrans_k(const float* __restrict__ in, float* __restrict__ out)
{
    int idx = blockIdx.x * blockDim.x + threadIdx.x;   // float4 index
    int d4  = idx & 15;
    int g   = (idx >> 4) & 7;
    int row = idx >> 7;
    int b = row >> 11, s = row & 2047;
    float4 v = ((const float4*)in)[idx];
    ((float4*)out)[((size_t)(b * NKV + g) * SEQ + s) * 16 + d4] = v;
}

// ---------------- Flash attention: 128-q x 64-k tiles, causal -----------------
#define ATTN_SMEM ((64*128 + 64*64 + 64*64 + 128*64) * 4)

__global__ __launch_bounds__(256) void attn_k(
    const float* __restrict__ Qr, const float* __restrict__ Kr,
    const float* __restrict__ Vr, float* __restrict__ ctx)
{
    extern __shared__ float sm[];
    float* Qt = sm;                 // [64][128]
    float* Kt = Qt + 64 * 128;      // [64][64]
    float* Vs = Kt + 64 * 64;       // [64][64]
    float* P  = Vs + 64 * 64;       // [128][64]

    const int bh = blockIdx.y;                 // b*32 + h
    const int b = bh >> 5, h = bh & 31, g = h >> 2;
    const int q0 = blockIdx.x * 128;
    const int tid = threadIdx.x;
    const int tx = tid & 15, ty = tid >> 4;    // 16 x 16 thread grid

    const float* Qbase = Qr + ((size_t)bh * SEQ + q0) * HD;
    const float* Kbase = Kr + (size_t)(b * NKV + g) * SEQ * HD;
    const float* Vbase = Vr + (size_t)(b * NKV + g) * SEQ * HD;

    // load Q tile transposed: Qt[d][q]
    {
        int q = tid & 127, half = tid >> 7;
        const float* qp = Qbase + q * HD + half * 32;
        #pragma unroll
        for (int i = 0; i < 8; i++) {
            float4 v = *(const float4*)(qp + i * 4);
            int d = half * 32 + i * 4;
            Qt[(d+0)*128 + q] = v.x; Qt[(d+1)*128 + q] = v.y;
            Qt[(d+2)*128 + q] = v.z; Qt[(d+3)*128 + q] = v.w;
        }
    }

    float m_[8], l_[8], acc[8][4];
    #pragma unroll
    for (int i = 0; i < 8; i++) {
        m_[i] = -1e30f; l_[i] = 0.f;
        #pragma unroll
        for (int j = 0; j < 4; j++) acc[i][j] = 0.f;
    }

    const int ntiles = q0 / 64 + 2;
    for (int t = 0; t < ntiles; t++) {
        const int k0 = t * 64;
        __syncthreads();
        // load K tile transposed Kt[d][k], V tile straight Vs[k][d]
        {
            int k = tid & 63, part = tid >> 6;
            const float* kp = Kbase + (size_t)(k0 + k) * HD + part * 16;
            #pragma unroll
            for (int i = 0; i < 4; i++) {
                float4 v = *(const float4*)(kp + i * 4);
                int d = part * 16 + i * 4;
                Kt[(d+0)*64 + k] = v.x; Kt[(d+1)*64 + k] = v.y;
                Kt[(d+2)*64 + k] = v.z; Kt[(d+3)*64 + k] = v.w;
            }
            const float4* vp = (const float4*)(Vbase + (size_t)k0 * HD);
            float4* vsp = (float4*)Vs;
            #pragma unroll
            for (int i = 0; i < 4; i++) vsp[tid + i * 256] = vp[tid + i * 256];
        }
        __syncthreads();

        // scores S[q][k] = Q·K^T  (8x4 per-thread tile)
        float s[8][4];
        #pragma unroll
        for (int i = 0; i < 8; i++)
            #pragma unroll
            for (int j = 0; j < 4; j++) s[i][j] = 0.f;

        #pragma unroll 8
        for (int d = 0; d < 64; d++) {
            float a[8], bb[4];
            *(float4*)&a[0]  = *(const float4*)&Qt[d*128 + ty*8];
            *(float4*)&a[4]  = *(const float4*)&Qt[d*128 + ty*8 + 4];
            *(float4*)&bb[0] = *(const float4*)&Kt[d*64 + tx*4];
            #pragma unroll
            for (int i = 0; i < 8; i++)
                #pragma unroll
                for (int j = 0; j < 4; j++)
                    s[i][j] = fmaf(a[i], bb[j], s[i][j]);
        }

        // scale + causal mask
        const bool do_mask = (k0 + 63 > q0);
        #pragma unroll
        for (int i = 0; i < 8; i++) {
            const int qg = q0 + ty*8 + i;
            #pragma unroll
            for (int j = 0; j < 4; j++) {
                float v = s[i][j] * 0.125f;           // 1/sqrt(64)
                if (do_mask && (k0 + tx*4 + j > qg)) v = -1e30f;
                s[i][j] = v;
            }
        }

        // online softmax across the 16 tx lanes
        #pragma unroll
        for (int i = 0; i < 8; i++) {
            float tm = fmaxf(fmaxf(s[i][0], s[i][1]), fmaxf(s[i][2], s[i][3]));
            tm = fmaxf(tm, __shfl_xor_sync(0xffffffffu, tm, 1));
            tm = fmaxf(tm, __shfl_xor_sync(0xffffffffu, tm, 2));
            tm = fmaxf(tm, __shfl_xor_sync(0xffffffffu, tm, 4));
            tm = fmaxf(tm, __shfl_xor_sync(0xffffffffu, tm, 8));
            float mn = fmaxf(m_[i], tm);
            float alpha = __expf(m_[i] - mn);
            m_[i] = mn;
            float rs = 0.f;
            #pragma unroll
            for (int j = 0; j < 4; j++) {
                float p = __expf(s[i][j] - mn);
                s[i][j] = p; rs += p;
            }
            rs += __shfl_xor_sync(0xffffffffu, rs, 1);
            rs += __shfl_xor_sync(0xffffffffu, rs, 2);
            rs += __shfl_xor_sync(0xffffffffu, rs, 4);
            rs += __shfl_xor_sync(0xffffffffu, rs, 8);
            l_[i] = l_[i] * alpha + rs;
            #pragma unroll
            for (int j = 0; j < 4; j++) acc[i][j] *= alpha;
            *(float4*)&P[(ty*8 + i)*64 + tx*4] =
                make_float4(s[i][0], s[i][1], s[i][2], s[i][3]);
        }
        __syncwarp();   // P rows produced/consumed within the same warp

        // O += P @ V
        #pragma unroll 4
        for (int k = 0; k < 64; k++) {
            float4 v4 = *(const float4*)&Vs[k*64 + tx*4];
            #pragma unroll
            for (int i = 0; i < 8; i++) {
                float p = P[(ty*8 + i)*64 + k];
                acc[i][0] = fmaf(p, v4.x, acc[i][0]);
                acc[i][1] = fmaf(p, v4.y, acc[i][1]);
                acc[i][2] = fmaf(p, v4.z, acc[i][2]);
                acc[i][3] = fmaf(p, v4.w, acc[i][3]);
            }
        }
    }

    // epilogue: write context as [B*S, NH*HD]
    #pragma unroll
    for (int i = 0; i < 8; i++) {
        float inv = 1.f / l_[i];
        int qg = q0 + ty*8 + i;
        float* cp = ctx + ((size_t)(b * SEQ + qg)) * DOUT + h * HD + tx*4;
        *(float4*)cp = make_float4(acc[i][0]*inv, acc[i][1]*inv,
                                   acc[i][2]*inv, acc[i][3]*inv);
    }
}

// ------------------------------- launcher -------------------------------------
extern "C" void kernel_launch(void* const* d_in, const int* in_sizes, int n_in,
                              void* d_out, int out_size)
{
    const float* x    = (const float*)d_in[0];
    const float* Wq   = (const float*)d_in[1];
    const float* Wk   = (const float*)d_in[2];
    const float* Wv   = (const float*)d_in[3];
    const float* Wo   = (const float*)d_in[4];
    const float* cosb = (const float*)d_in[5];
    const float* sinb = (const float*)d_in[6];
    float* out = (float*)d_out;

    float *pQ, *pK, *pV, *pQr, *pKr, *pVr, *pCtx;
    cudaGetSymbolAddress((void**)&pQ,   g_Q);
    cudaGetSymbolAddress((void**)&pK,   g_K);
    cudaGetSymbolAddress((void**)&pV,   g_V);
    cudaGetSymbolAddress((void**)&pQr,  g_Qr);
    cudaGetSymbolAddress((void**)&pKr,  g_Kr);
    cudaGetSymbolAddress((void**)&pVr,  g_Vr);
    cudaGetSymbolAddress((void**)&pCtx, g_ctx);

    dim3 thr(256);

    cudaFuncSetAttribute(sgemm_tc, cudaFuncAttributeMaxDynamicSharedMemorySize, SGEMM_SMEM);

    // QKV projections (tf32 tensor core)
    sgemm_tc<<<dim3(DOUT/128, ROWS/128), thr, SGEMM_SMEM>>>(x, Wq, pQ, ROWS, DOUT, DIN);
    sgemm_tc<<<dim3(DKV /128, ROWS/128), thr, SGEMM_SMEM>>>(x, Wk, pK, ROWS, DKV, DIN);
    sgemm_tc<<<dim3(DKV /128, ROWS/128), thr, SGEMM_SMEM>>>(x, Wv, pV, ROWS, DKV, DIN);

    // RoPE + head-major transposes
    rope_k<<<(ROWS * NH  * 32) / 256, thr>>>(pQ, cosb, sinb, pQr, NH);
    rope_k<<<(ROWS * NKV * 32) / 256, thr>>>(pK, cosb, sinb, pKr, NKV);
    vtrans_k<<<(ROWS * DKV / 4) / 256, thr>>>(pV, pVr);

    // causal flash attention (fp32 — keeps error budget for tf32 GEMMs)
    cudaFuncSetAttribute(attn_k, cudaFuncAttributeMaxDynamicSharedMemorySize, ATTN_SMEM);
    attn_k<<<dim3(SEQ/128, BATCH*NH), thr, ATTN_SMEM>>>(pQr, pKr, pVr, pCtx);

    // output projection (tf32 tensor core)
    sgemm_tc<<<dim3(DOUT/128, ROWS/128), thr, SGEMM_SMEM>>>(pCtx, Wo, out, ROWS, DOUT, DIN);
}

// round 3
// speedup vs baseline: 2.0614x; 1.3995x over previous
#include <cuda_runtime.h>
#include <math.h>
#include <stdint.h>

#define BATCH 2
#define SEQ   2048
#define DIN   2048
#define DOUT  2048
#define NH    32
#define NKV   8
#define HD    64
#define ROWS  (BATCH*SEQ)    /* 4096 */
#define DKV   (NKV*HD)       /* 512  */

// ---------------- scratch (static device arrays; no allocation) ----------------
__device__ float    g_Q  [ROWS*DOUT];
__device__ float    g_K  [ROWS*DKV];
__device__ float    g_V  [ROWS*DKV];
__device__ uint32_t g_Qr [ROWS*DOUT];   // [B,NH,S,HD]  tf32
__device__ uint32_t g_Kr [ROWS*DKV];    // [B,NKV,S,HD] tf32
__device__ uint32_t g_Vr [ROWS*DKV];    // [B,NKV,S,HD] tf32
__device__ float    g_ctx[ROWS*DOUT];   // [B*S, NH*HD]

__device__ __forceinline__ uint32_t f2tf(float f) {
    uint32_t r;
    asm("cvt.rna.tf32.f32 %0, %1;" : "=r"(r) : "f"(f));
    return r;
}

__device__ __forceinline__ void mma_tf32(float* c, const uint32_t* a,
                                         uint32_t b0, uint32_t b1) {
    asm volatile(
        "mma.sync.aligned.m16n8k8.row.col.f32.tf32.tf32.f32 "
        "{%0,%1,%2,%3}, {%4,%5,%6,%7}, {%8,%9}, {%0,%1,%2,%3};"
        : "+f"(c[0]), "+f"(c[1]), "+f"(c[2]), "+f"(c[3])
        : "r"(a[0]), "r"(a[1]), "r"(a[2]), "r"(a[3]), "r"(b0), "r"(b1));
}

// ---------------- tf32 tensor-core GEMM (unchanged from R2) --------------------
#define TCK      32
#define TSTRIDE  136
#define SGEMM_SMEM (2 * TCK * TSTRIDE * 2 * 4)   /* 69632 bytes */

__global__ __launch_bounds__(256) void sgemm_tc(
    const float* __restrict__ A, const float* __restrict__ B,
    float* __restrict__ C, int M, int N, int K)
{
    extern __shared__ uint32_t sm_u[];
    uint32_t* As = sm_u;                         // [2][32][136]
    uint32_t* Bs = sm_u + 2 * TCK * TSTRIDE;

    const int tid  = threadIdx.x;
    const int warp = tid >> 5, lane = tid & 31;
    const int g    = lane >> 2, t = lane & 3;
    const int wm   = (warp & 3) * 32;
    const int wn   = (warp >> 2) * 64;
    const int row0 = blockIdx.y * 128, col0 = blockIdx.x * 128;

    const int ar = tid >> 1, ac = (tid & 1) * 16;
    const int br = tid >> 3, bc = (tid & 7) * 16;

    const float* Ap = A + (size_t)(row0 + ar) * K + ac;
    const float* Bp = B + (size_t)br * N + col0 + bc;

    float acc[2][8][4];
    #pragma unroll
    for (int mi = 0; mi < 2; mi++)
        #pragma unroll
        for (int ni = 0; ni < 8; ni++)
            #pragma unroll
            for (int r = 0; r < 4; r++) acc[mi][ni][r] = 0.f;

    float4 av[4], bv[4];

    auto LOADG = [&](int k0) {
        #pragma unroll
        for (int i = 0; i < 4; i++) av[i] = *(const float4*)(Ap + k0 + i * 4);
        #pragma unroll
        for (int i = 0; i < 4; i++) bv[i] = *(const float4*)(Bp + (size_t)k0 * N + i * 4);
    };

    auto STORE = [&](int buf) {
        #pragma unroll
        for (int i = 0; i < 4; i++) {
            const int k = ac + i * 4;
            As[(buf * TCK + k + 0) * TSTRIDE + ar] = f2tf(av[i].x);
            As[(buf * TCK + k + 1) * TSTRIDE + ar] = f2tf(av[i].y);
            As[(buf * TCK + k + 2) * TSTRIDE + ar] = f2tf(av[i].z);
            As[(buf * TCK + k + 3) * TSTRIDE + ar] = f2tf(av[i].w);
        }
        #pragma unroll
        for (int i = 0; i < 4; i++) {
            uint4 w;
            w.x = f2tf(bv[i].x); w.y = f2tf(bv[i].y);
            w.z = f2tf(bv[i].z); w.w = f2tf(bv[i].w);
            *(uint4*)&Bs[(buf * TCK + br) * TSTRIDE + bc + i * 4] = w;
        }
    };

    auto MMASTEP = [&](int buf) {
        #pragma unroll
        for (int ks = 0; ks < 4; ks++) {
            const int kb = buf * TCK + ks * 8;
            uint32_t a[2][4], b[8][2];
            #pragma unroll
            for (int mi = 0; mi < 2; mi++) {
                const int m0 = wm + mi * 16 + g;
                a[mi][0] = As[(kb + t    ) * TSTRIDE + m0];
                a[mi][1] = As[(kb + t    ) * TSTRIDE + m0 + 8];
                a[mi][2] = As[(kb + t + 4) * TSTRIDE + m0];
                a[mi][3] = As[(kb + t + 4) * TSTRIDE + m0 + 8];
            }
            #pragma unroll
            for (int ni = 0; ni < 8; ni++) {
                const int n0 = wn + ni * 8 + g;
                b[ni][0] = Bs[(kb + t    ) * TSTRIDE + n0];
                b[ni][1] = Bs[(kb + t + 4) * TSTRIDE + n0];
            }
            #pragma unroll
            for (int mi = 0; mi < 2; mi++)
                #pragma unroll
                for (int ni = 0; ni < 8; ni++)
                    mma_tf32(acc[mi][ni], a[mi], b[ni][0], b[ni][1]);
        }
    };

    LOADG(0);
    STORE(0);
    __syncthreads();

    const int niter = K / TCK;
    for (int it = 0; it < niter; it++) {
        const int buf = it & 1;
        if (it + 1 < niter) LOADG((it + 1) * TCK);
        MMASTEP(buf);
        if (it + 1 < niter) STORE(buf ^ 1);
        __syncthreads();
    }

    #pragma unroll
    for (int mi = 0; mi < 2; mi++)
        #pragma unroll
        for (int ni = 0; ni < 8; ni++) {
            const int r = row0 + wm + mi * 16 + g;
            const int c = col0 + wn + ni * 8 + t * 2;
            *(float2*)(C + (size_t)r * N + c) =
                make_float2(acc[mi][ni][0], acc[mi][ni][1]);
            *(float2*)(C + (size_t)(r + 8) * N + c) =
                make_float2(acc[mi][ni][2], acc[mi][ni][3]);
        }
}

// ---------------- RoPE + transpose + tf32 convert ------------------------------
__global__ void rope_k(const float* __restrict__ in, const float* __restrict__ cosb,
                       const float* __restrict__ sinb, uint32_t* __restrict__ out,
                       int nheads)
{
    int idx = blockIdx.x * blockDim.x + threadIdx.x;   // (row, h, d<32)
    int d = idx & 31;
    int h = (idx >> 5) % nheads;
    int row = idx / (nheads * 32);
    int b = row >> 11, s = row & 2047;

    const float* ip = in + (size_t)row * (nheads * HD) + h * HD;
    float x1 = ip[d], x2 = ip[d + 32];
    float c1 = cosb[s * HD + d],      s1 = sinb[s * HD + d];
    float c2 = cosb[s * HD + d + 32], s2 = sinb[s * HD + d + 32];

    uint32_t* op = out + ((size_t)(b * nheads + h) * SEQ + s) * HD;
    op[d]      = f2tf(x1 * c1 - x2 * s1);
    op[d + 32] = f2tf(x2 * c2 + x1 * s2);
}

// ---------------- V transpose + tf32 convert -----------------------------------
__global__ void vtrans_k(const float* __restrict__ in, uint32_t* __restrict__ out)
{
    int idx = blockIdx.x * blockDim.x + threadIdx.x;   // element index
    int d   = idx & 63;
    int gg  = (idx >> 6) & 7;
    int row = idx >> 9;
    int b = row >> 11, s = row & 2047;
    float v = in[idx];
    out[((size_t)(b * NKV + gg) * SEQ + s) * HD + d] = f2tf(v);
}

// ---------------- tf32 tensor-core flash attention -----------------------------
// Block: 128 q-rows, 8 warps x 16 q-rows each; loops 64-k tiles (causal).
#define KST 72
#define ATTN_SMEM ((128*KST + 64*KST + 64*KST) * 4)   /* 73728 bytes */

__global__ __launch_bounds__(256) void attn_tc(
    const uint32_t* __restrict__ Qr, const uint32_t* __restrict__ Kr,
    const uint32_t* __restrict__ Vr, float* __restrict__ ctx)
{
    extern __shared__ uint32_t smu[];
    uint32_t* Pq = smu;               // [128][72]  Q staging, then P tiles
    uint32_t* Ks = smu + 128 * KST;   // [64][72]
    uint32_t* Vs = Ks  + 64  * KST;   // [64][72]

    const int bh = blockIdx.y;                    // b*32 + h
    const int b = bh >> 5, h = bh & 31, g2 = h >> 2;
    const int qt = gridDim.x - 1 - blockIdx.x;    // heavy tiles first
    const int q0 = qt * 128;
    const int tid = threadIdx.x;
    const int warp = tid >> 5, lane = tid & 31;
    const int g = lane >> 2, t = lane & 3;
    const int wq = warp * 16;

    const uint32_t* Qbase = Qr + ((size_t)bh * SEQ + q0) * HD;
    const uint32_t* Kbase = Kr + (size_t)(b * NKV + g2) * SEQ * HD;
    const uint32_t* Vbase = Vr + (size_t)(b * NKV + g2) * SEQ * HD;

    // ---- stage Q (coalesced) then pull fragments into registers
    #pragma unroll
    for (int i = 0; i < 8; i++) {
        int idx = i * 256 + tid;                 // uint4 index, 16 per row
        int r = idx >> 4, c = (idx & 15) * 4;
        *(uint4*)&Pq[r * KST + c] = *(const uint4*)&Qbase[r * HD + c];
    }
    __syncthreads();

    uint32_t qf[8][4];
    #pragma unroll
    for (int s = 0; s < 8; s++) {
        qf[s][0] = Pq[(wq + g    ) * KST + s * 8 + t];
        qf[s][1] = Pq[(wq + g + 8) * KST + s * 8 + t];
        qf[s][2] = Pq[(wq + g    ) * KST + s * 8 + t + 4];
        qf[s][3] = Pq[(wq + g + 8) * KST + s * 8 + t + 4];
    }

    float o[8][4];
    #pragma unroll
    for (int ni = 0; ni < 8; ni++)
        #pragma unroll
        for (int r = 0; r < 4; r++) o[ni][r] = 0.f;
    float m0 = -1e30f, m1 = -1e30f, l0 = 0.f, l1 = 0.f;

    const int ntiles = qt * 2 + 2;
    for (int tt = 0; tt < ntiles; tt++) {
        const int k0 = tt * 64;
        __syncthreads();
        // stage K, V tiles (coalesced)
        #pragma unroll
        for (int i = 0; i < 4; i++) {
            int idx = i * 256 + tid;
            int r = idx >> 4, c = (idx & 15) * 4;
            *(uint4*)&Ks[r * KST + c] = *(const uint4*)&Kbase[(size_t)(k0 + r) * HD + c];
            *(uint4*)&Vs[r * KST + c] = *(const uint4*)&Vbase[(size_t)(k0 + r) * HD + c];
        }
        __syncthreads();

        // ---- S = Q @ K^T  (16q x 64k per warp)
        float s[8][4];
        #pragma unroll
        for (int ni = 0; ni < 8; ni++)
            #pragma unroll
            for (int r = 0; r < 4; r++) s[ni][r] = 0.f;

        #pragma unroll
        for (int ds = 0; ds < 8; ds++) {
            #pragma unroll
            for (int ni = 0; ni < 8; ni++) {
                uint32_t b0 = Ks[(ni * 8 + g) * KST + ds * 8 + t];
                uint32_t b1 = Ks[(ni * 8 + g) * KST + ds * 8 + t + 4];
                mma_tf32(s[ni], qf[ds], b0, b1);
            }
        }

        // ---- scale + causal mask
        const bool do_mask = (k0 + 63 > q0);
        const int qg0 = q0 + wq + g, qg1 = qg0 + 8;
        #pragma unroll
        for (int ni = 0; ni < 8; ni++) {
            #pragma unroll
            for (int r = 0; r < 4; r++) {
                float v = s[ni][r] * 0.125f;      // 1/sqrt(64)
                if (do_mask) {
                    int kg = k0 + ni * 8 + 2 * t + (r & 1);
                    int qg = (r >= 2) ? qg1 : qg0;
                    if (kg > qg) v = -1e30f;
                }
                s[ni][r] = v;
            }
        }

        // ---- online softmax (rows g -> m0/l0, rows g+8 -> m1/l1)
        float tm0 = -1e30f, tm1 = -1e30f;
        #pragma unroll
        for (int ni = 0; ni < 8; ni++) {
            tm0 = fmaxf(tm0, fmaxf(s[ni][0], s[ni][1]));
            tm1 = fmaxf(tm1, fmaxf(s[ni][2], s[ni][3]));
        }
        tm0 = fmaxf(tm0, __shfl_xor_sync(0xffffffffu, tm0, 1));
        tm0 = fmaxf(tm0, __shfl_xor_sync(0xffffffffu, tm0, 2));
        tm1 = fmaxf(tm1, __shfl_xor_sync(0xffffffffu, tm1, 1));
        tm1 = fmaxf(tm1, __shfl_xor_sync(0xffffffffu, tm1, 2));

        float mn0 = fmaxf(m0, tm0), mn1 = fmaxf(m1, tm1);
        float a0 = __expf(m0 - mn0), a1 = __expf(m1 - mn1);
        m0 = mn0; m1 = mn1;

        float rs0 = 0.f, rs1 = 0.f;
        #pragma unroll
        for (int ni = 0; ni < 8; ni++) {
            s[ni][0] = __expf(s[ni][0] - mn0);
            s[ni][1] = __expf(s[ni][1] - mn0);
            s[ni][2] = __expf(s[ni][2] - mn1);
            s[ni][3] = __expf(s[ni][3] - mn1);
            rs0 += s[ni][0] + s[ni][1];
            rs1 += s[ni][2] + s[ni][3];
        }
        rs0 += __shfl_xor_sync(0xffffffffu, rs0, 1);
        rs0 += __shfl_xor_sync(0xffffffffu, rs0, 2);
        rs1 += __shfl_xor_sync(0xffffffffu, rs1, 1);
        rs1 += __shfl_xor_sync(0xffffffffu, rs1, 2);
        l0 = l0 * a0 + rs0;
        l1 = l1 * a1 + rs1;

        #pragma unroll
        for (int ni = 0; ni < 8; ni++) {
            o[ni][0] *= a0; o[ni][1] *= a0;
            o[ni][2] *= a1; o[ni][3] *= a1;
        }

        // ---- P -> smem (tf32), rearrange into A-fragment layout
        #pragma unroll
        for (int ni = 0; ni < 8; ni++) {
            uint2 w0 = make_uint2(f2tf(s[ni][0]), f2tf(s[ni][1]));
            uint2 w1 = make_uint2(f2tf(s[ni][2]), f2tf(s[ni][3]));
            *(uint2*)&Pq[(wq + g    ) * KST + ni * 8 + 2 * t] = w0;
            *(uint2*)&Pq[(wq + g + 8) * KST + ni * 8 + 2 * t] = w1;
        }
        __syncwarp();

        // ---- O += P @ V
        #pragma unroll
        for (int ks = 0; ks < 8; ks++) {
            uint32_t a[4];
            a[0] = Pq[(wq + g    ) * KST + ks * 8 + t];
            a[1] = Pq[(wq + g + 8) * KST + ks * 8 + t];
            a[2] = Pq[(wq + g    ) * KST + ks * 8 + t + 4];
            a[3] = Pq[(wq + g + 8) * KST + ks * 8 + t + 4];
            #pragma unroll
            for (int ni = 0; ni < 8; ni++) {
                uint32_t b0 = Vs[(ks * 8 + t    ) * KST + ni * 8 + g];
                uint32_t b1 = Vs[(ks * 8 + t + 4) * KST + ni * 8 + g];
                mma_tf32(o[ni], a, b0, b1);
            }
        }
    }

    // ---- epilogue: ctx[b*SEQ + q][h*64 + d]
    float inv0 = 1.f / l0, inv1 = 1.f / l1;
    const int qg0 = q0 + wq + g, qg1 = qg0 + 8;
    #pragma unroll
    for (int ni = 0; ni < 8; ni++) {
        int c = h * HD + ni * 8 + 2 * t;
        *(float2*)&ctx[(size_t)(b * SEQ + qg0) * DOUT + c] =
            make_float2(o[ni][0] * inv0, o[ni][1] * inv0);
        *(float2*)&ctx[(size_t)(b * SEQ + qg1) * DOUT + c] =
            make_float2(o[ni][2] * inv1, o[ni][3] * inv1);
    }
}

// ------------------------------- launcher -------------------------------------
extern "C" void kernel_launch(void* const* d_in, const int* in_sizes, int n_in,
                              void* d_out, int out_size)
{
    const float* x    = (const float*)d_in[0];
    const float* Wq   = (const float*)d_in[1];
    const float* Wk   = (const float*)d_in[2];
    const float* Wv   = (const float*)d_in[3];
    const float* Wo   = (const float*)d_in[4];
    const float* cosb = (const float*)d_in[5];
    const float* sinb = (const float*)d_in[6];
    float* out = (float*)d_out;

    float *pQ, *pK, *pV, *pCtx;
    uint32_t *pQr, *pKr, *pVr;
    cudaGetSymbolAddress((void**)&pQ,   g_Q);
    cudaGetSymbolAddress((void**)&pK,   g_K);
    cudaGetSymbolAddress((void**)&pV,   g_V);
    cudaGetSymbolAddress((void**)&pQr,  g_Qr);
    cudaGetSymbolAddress((void**)&pKr,  g_Kr);
    cudaGetSymbolAddress((void**)&pVr,  g_Vr);
    cudaGetSymbolAddress((void**)&pCtx, g_ctx);

    dim3 thr(256);

    cudaFuncSetAttribute(sgemm_tc, cudaFuncAttributeMaxDynamicSharedMemorySize, SGEMM_SMEM);
    cudaFuncSetAttribute(attn_tc,  cudaFuncAttributeMaxDynamicSharedMemorySize, ATTN_SMEM);

    // QKV projections (tf32 tensor core)
    sgemm_tc<<<dim3(DOUT/128, ROWS/128), thr, SGEMM_SMEM>>>(x, Wq, pQ, ROWS, DOUT, DIN);
    sgemm_tc<<<dim3(DKV /128, ROWS/128), thr, SGEMM_SMEM>>>(x, Wk, pK, ROWS, DKV, DIN);
    sgemm_tc<<<dim3(DKV /128, ROWS/128), thr, SGEMM_SMEM>>>(x, Wv, pV, ROWS, DKV, DIN);

    // RoPE + head-major transposes + tf32 preconvert
    rope_k<<<(ROWS * NH  * 32) / 256, thr>>>(pQ, cosb, sinb, pQr, NH);
    rope_k<<<(ROWS * NKV * 32) / 256, thr>>>(pK, cosb, sinb, pKr, NKV);
    vtrans_k<<<(ROWS * DKV) / 256, thr>>>(pV, pVr);

    // causal flash attention (tf32 tensor core)
    attn_tc<<<dim3(SEQ/128, BATCH*NH), thr, ATTN_SMEM>>>(pQr, pKr, pVr, pCtx);

    // output projection (tf32 tensor core)
    sgemm_tc<<<dim3(DOUT/128, ROWS/128), thr, SGEMM_SMEM>>>(pCtx, Wo, out, ROWS, DOUT, DIN);
}

// round 4
// speedup vs baseline: 3.2753x; 1.5889x over previous
#include <cuda_runtime.h>
#include <math.h>
#include <stdint.h>

#define BATCH 2
#define SEQ   2048
#define DIN   2048
#define DOUT  2048
#define NH    32
#define NKV   8
#define HD    64
#define ROWS  (BATCH*SEQ)    /* 4096 */
#define DKV   (NKV*HD)       /* 512  */

// ---------------- scratch (static device arrays; no allocation) ----------------
__device__ float    g_Q  [ROWS*DOUT];
__device__ float    g_K  [ROWS*DKV];
__device__ float    g_V  [ROWS*DKV];
__device__ uint32_t g_Qr [ROWS*DOUT];   // [B,NH,S,HD]  tf32
__device__ uint32_t g_Kr [ROWS*DKV];    // [B,NKV,S,HD] tf32
__device__ uint32_t g_Vr [ROWS*DKV];    // [B,NKV,S,HD] tf32
__device__ float    g_ctx[ROWS*DOUT];   // [B*S, NH*HD]

__device__ __forceinline__ uint32_t f2tf(float f) {
    uint32_t r;
    asm("cvt.rna.tf32.f32 %0, %1;" : "=r"(r) : "f"(f));
    return r;
}
__device__ __forceinline__ float tfm(uint32_t u) { return __uint_as_float(u); }

__device__ __forceinline__ void mma_tf32(float* c, const uint32_t* a,
                                         uint32_t b0, uint32_t b1) {
    asm volatile(
        "mma.sync.aligned.m16n8k8.row.col.f32.tf32.tf32.f32 "
        "{%0,%1,%2,%3}, {%4,%5,%6,%7}, {%8,%9}, {%0,%1,%2,%3};"
        : "+f"(c[0]), "+f"(c[1]), "+f"(c[2]), "+f"(c[3])
        : "r"(a[0]), "r"(a[1]), "r"(a[2]), "r"(a[3]), "r"(b0), "r"(b1));
}

__device__ __forceinline__ void cp16(uint32_t smem_byte, const void* g) {
    asm volatile("cp.async.cg.shared.global [%0], [%1], 16;\n"
                 :: "r"(smem_byte), "l"(g));
}
__device__ __forceinline__ void cp_commit() {
    asm volatile("cp.async.commit_group;\n" ::);
}
template <int N>
__device__ __forceinline__ void cp_wait() {
    asm volatile("cp.async.wait_group %0;\n" :: "n"(N));
}

// ================= tf32 GEMM, cp.async 2-stage pipeline ========================
// C[M,N] = A[M,K] @ B[K,N], fp32 in/out, tf32 MMA (convert at fragment load).
// A smem row-major stride 36 (bank 4g+t), B smem k-major stride 136 (bank 8t+g).
#define AST 36
#define BST 136
#define SGEMM_SMEM ((2*128*AST + 2*32*BST) * 4)   /* 71680 bytes */

__global__ __launch_bounds__(256) void sgemm_tc(
    const float* __restrict__ A, const float* __restrict__ B,
    float* __restrict__ C, int M, int N, int K)
{
    extern __shared__ float smf[];
    float* As = smf;                    // [2][128][36]
    float* Bs = smf + 2 * 128 * AST;    // [2][32][136]

    const int tid  = threadIdx.x;
    const int warp = tid >> 5, lane = tid & 31;
    const int g    = lane >> 2, t = lane & 3;
    const int wm   = (warp & 3) * 32;
    const int wn   = (warp >> 2) * 64;
    const int row0 = blockIdx.y * 128, col0 = blockIdx.x * 128;

    const uint32_t sA = (uint32_t)__cvta_generic_to_shared(As);
    const uint32_t sB = (uint32_t)__cvta_generic_to_shared(Bs);

    const int a_c = (tid & 7) * 4,  a_r = tid >> 3;    // 32 rows/pass, 4 passes
    const int b_c = (tid & 31) * 4, b_r = tid >> 5;    // 8 rows/pass, 4 passes

    auto LOAD = [&](int k0, int buf) {
        const float* ap = A + (size_t)(row0 + a_r) * K + k0 + a_c;
        uint32_t da = sA + (uint32_t)(buf * 128 * AST + a_r * AST + a_c) * 4;
        #pragma unroll
        for (int i = 0; i < 4; i++)
            cp16(da + i * 32 * AST * 4, ap + (size_t)i * 32 * K);
        const float* bp = B + (size_t)(k0 + b_r) * N + col0 + b_c;
        uint32_t db = sB + (uint32_t)(buf * 32 * BST + b_r * BST + b_c) * 4;
        #pragma unroll
        for (int i = 0; i < 4; i++)
            cp16(db + i * 8 * BST * 4, bp + (size_t)i * 8 * N);
    };

    float acc[2][8][4];
    #pragma unroll
    for (int mi = 0; mi < 2; mi++)
        #pragma unroll
        for (int ni = 0; ni < 8; ni++)
            #pragma unroll
            for (int r = 0; r < 4; r++) acc[mi][ni][r] = 0.f;

    LOAD(0, 0);
    cp_commit();

    const int niter = K / 32;
    for (int it = 0; it < niter; it++) {
        const int buf = it & 1;
        if (it + 1 < niter) {
            LOAD((it + 1) * 32, buf ^ 1);
            cp_commit();
            cp_wait<1>();
        } else {
            cp_wait<0>();
        }
        __syncthreads();

        const float* Asb = As + buf * 128 * AST;
        const float* Bsb = Bs + buf * 32 * BST;
        #pragma unroll
        for (int ks = 0; ks < 4; ks++) {
            const int kb = ks * 8;
            uint32_t a[2][4], b[8][2];
            #pragma unroll
            for (int mi = 0; mi < 2; mi++) {
                const int m0 = wm + mi * 16 + g;
                a[mi][0] = f2tf(Asb[(m0    ) * AST + kb + t]);
                a[mi][1] = f2tf(Asb[(m0 + 8) * AST + kb + t]);
                a[mi][2] = f2tf(Asb[(m0    ) * AST + kb + t + 4]);
                a[mi][3] = f2tf(Asb[(m0 + 8) * AST + kb + t + 4]);
            }
            #pragma unroll
            for (int ni = 0; ni < 8; ni++) {
                const int n0 = wn + ni * 8 + g;
                b[ni][0] = f2tf(Bsb[(kb + t    ) * BST + n0]);
                b[ni][1] = f2tf(Bsb[(kb + t + 4) * BST + n0]);
            }
            #pragma unroll
            for (int mi = 0; mi < 2; mi++)
                #pragma unroll
                for (int ni = 0; ni < 8; ni++)
                    mma_tf32(acc[mi][ni], a[mi], b[ni][0], b[ni][1]);
        }
        __syncthreads();
    }

    #pragma unroll
    for (int mi = 0; mi < 2; mi++)
        #pragma unroll
        for (int ni = 0; ni < 8; ni++) {
            const int r = row0 + wm + mi * 16 + g;
            const int c = col0 + wn + ni * 8 + t * 2;
            *(float2*)(C + (size_t)r * N + c) =
                make_float2(acc[mi][ni][0], acc[mi][ni][1]);
            *(float2*)(C + (size_t)(r + 8) * N + c) =
                make_float2(acc[mi][ni][2], acc[mi][ni][3]);
        }
}

// ---------------- RoPE + transpose + tf32 convert (templated heads) ------------
template <int NHEADS, int LOGNH>
__global__ void rope_k(const float* __restrict__ in, const float* __restrict__ cosb,
                       const float* __restrict__ sinb, uint32_t* __restrict__ out)
{
    int idx = blockIdx.x * blockDim.x + threadIdx.x;   // (row, h, d<32)
    int d = idx & 31;
    int h = (idx >> 5) & (NHEADS - 1);
    int row = idx >> (5 + LOGNH);
    int b = row >> 11, s = row & 2047;

    const float* ip = in + (size_t)row * (NHEADS * HD) + h * HD;
    float x1 = ip[d], x2 = ip[d + 32];
    float c1 = cosb[s * HD + d],      s1 = sinb[s * HD + d];
    float c2 = cosb[s * HD + d + 32], s2 = sinb[s * HD + d + 32];

    uint32_t* op = out + ((size_t)(b * NHEADS + h) * SEQ + s) * HD;
    op[d]      = f2tf(x1 * c1 - x2 * s1);
    op[d + 32] = f2tf(x2 * c2 + x1 * s2);
}

// ---------------- V transpose + tf32 convert -----------------------------------
__global__ void vtrans_k(const float* __restrict__ in, uint32_t* __restrict__ out)
{
    int idx = blockIdx.x * blockDim.x + threadIdx.x;
    int d   = idx & 63;
    int gg  = (idx >> 6) & 7;
    int row = idx >> 9;
    int b = row >> 11, s = row & 2047;
    float v = in[idx];
    out[((size_t)(b * NKV + gg) * SEQ + s) * HD + d] = f2tf(v);
}

// ================= tf32 flash attention, cp.async double-buffered ==============
// 128 q-rows/block, 8 warps x 16 q-rows; 64-k tiles, causal, heavy-first.
// Pq/Ks stride 68 (bank 4g+t), Vs stride 72 (bank 8t+g).
#define QST 68
#define VST 72
#define ATTN_SMEM ((128*QST + 2*64*QST + 2*64*VST) * 4)   /* 106496 bytes */

__global__ __launch_bounds__(256) void attn_tc(
    const uint32_t* __restrict__ Qr, const uint32_t* __restrict__ Kr,
    const uint32_t* __restrict__ Vr, float* __restrict__ ctx)
{
    extern __shared__ uint32_t smu[];
    uint32_t* Pq = smu;                   // [128][68] Q staging, then P tiles
    uint32_t* Ks = smu + 128 * QST;       // [2][64][68]
    uint32_t* Vs = Ks  + 2 * 64 * QST;    // [2][64][72]

    const int bh = blockIdx.y;                    // b*32 + h
    const int b = bh >> 5, h = bh & 31, g2 = h >> 2;
    const int qt = gridDim.x - 1 - blockIdx.x;    // heavy tiles first
    const int q0 = qt * 128;
    const int tid = threadIdx.x;
    const int warp = tid >> 5, lane = tid & 31;
    const int g = lane >> 2, t = lane & 3;
    const int wq = warp * 16;

    const uint32_t* Qbase = Qr + ((size_t)bh * SEQ + q0) * HD;
    const uint32_t* Kbase = Kr + (size_t)(b * NKV + g2) * SEQ * HD;
    const uint32_t* Vbase = Vr + (size_t)(b * NKV + g2) * SEQ * HD;

    const uint32_t sK = (uint32_t)__cvta_generic_to_shared(Ks);
    const uint32_t sV = (uint32_t)__cvta_generic_to_shared(Vs);

    const int kc = (tid & 15) * 4, kr = tid >> 4;    // 16 rows/pass, 4 passes

    auto LOADKV = [&](int k0, int buf) {
        const uint32_t* kp = Kbase + (size_t)(k0 + kr) * HD + kc;
        const uint32_t* vp = Vbase + (size_t)(k0 + kr) * HD + kc;
        uint32_t dk = sK + (uint32_t)(buf * 64 * QST + kr * QST + kc) * 4;
        uint32_t dv = sV + (uint32_t)(buf * 64 * VST + kr * VST + kc) * 4;
        #pragma unroll
        for (int i = 0; i < 4; i++) {
            cp16(dk + i * 16 * QST * 4, kp + (size_t)i * 16 * HD);
            cp16(dv + i * 16 * VST * 4, vp + (size_t)i * 16 * HD);
        }
    };

    // prefetch tile 0, then stage Q
    LOADKV(0, 0);
    cp_commit();
    #pragma unroll
    for (int i = 0; i < 8; i++) {
        int idx = i * 256 + tid;                 // uint4 index, 16 per row
        int r = idx >> 4, c = (idx & 15) * 4;
        *(uint4*)&Pq[r * QST + c] = *(const uint4*)&Qbase[r * HD + c];
    }
    __syncthreads();

    uint32_t qf[8][4];
    #pragma unroll
    for (int s = 0; s < 8; s++) {
        qf[s][0] = Pq[(wq + g    ) * QST + s * 8 + t];
        qf[s][1] = Pq[(wq + g + 8) * QST + s * 8 + t];
        qf[s][2] = Pq[(wq + g    ) * QST + s * 8 + t + 4];
        qf[s][3] = Pq[(wq + g + 8) * QST + s * 8 + t + 4];
    }

    float o[8][4];
    #pragma unroll
    for (int ni = 0; ni < 8; ni++)
        #pragma unroll
        for (int r = 0; r < 4; r++) o[ni][r] = 0.f;
    float m0 = -1e30f, m1 = -1e30f, l0 = 0.f, l1 = 0.f;

    const int ntiles = qt * 2 + 2;
    for (int tt = 0; tt < ntiles; tt++) {
        const int buf = tt & 1;
        if (tt + 1 < ntiles) {
            LOADKV((tt + 1) * 64, buf ^ 1);
            cp_commit();
            cp_wait<1>();
        } else {
            cp_wait<0>();
        }
        __syncthreads();

        const uint32_t* Ksb = Ks + buf * 64 * QST;
        const uint32_t* Vsb = Vs + buf * 64 * VST;
        const int k0 = tt * 64;

        // ---- S = Q @ K^T
        float s[8][4];
        #pragma unroll
        for (int ni = 0; ni < 8; ni++)
            #pragma unroll
            for (int r = 0; r < 4; r++) s[ni][r] = 0.f;

        #pragma unroll
        for (int ds = 0; ds < 8; ds++) {
            #pragma unroll
            for (int ni = 0; ni < 8; ni++) {
                uint32_t b0 = Ksb[(ni * 8 + g) * QST + ds * 8 + t];
                uint32_t b1 = Ksb[(ni * 8 + g) * QST + ds * 8 + t + 4];
                mma_tf32(s[ni], qf[ds], b0, b1);
            }
        }

        // ---- scale + causal mask
        const bool do_mask = (k0 + 63 > q0);
        const int qg0 = q0 + wq + g, qg1 = qg0 + 8;
        #pragma unroll
        for (int ni = 0; ni < 8; ni++) {
            #pragma unroll
            for (int r = 0; r < 4; r++) {
                float v = s[ni][r] * 0.125f;      // 1/sqrt(64)
                if (do_mask) {
                    int kg = k0 + ni * 8 + 2 * t + (r & 1);
                    int qg = (r >= 2) ? qg1 : qg0;
                    if (kg > qg) v = -1e30f;
                }
                s[ni][r] = v;
            }
        }

        // ---- online softmax
        float tm0 = -1e30f, tm1 = -1e30f;
        #pragma unroll
        for (int ni = 0; ni < 8; ni++) {
            tm0 = fmaxf(tm0, fmaxf(s[ni][0], s[ni][1]));
            tm1 = fmaxf(tm1, fmaxf(s[ni][2], s[ni][3]));
        }
        tm0 = fmaxf(tm0, __shfl_xor_sync(0xffffffffu, tm0, 1));
        tm0 = fmaxf(tm0, __shfl_xor_sync(0xffffffffu, tm0, 2));
        tm1 = fmaxf(tm1, __shfl_xor_sync(0xffffffffu, tm1, 1));
        tm1 = fmaxf(tm1, __shfl_xor_sync(0xffffffffu, tm1, 2));

        float mn0 = fmaxf(m0, tm0), mn1 = fmaxf(m1, tm1);
        float a0 = __expf(m0 - mn0), a1 = __expf(m1 - mn1);
        m0 = mn0; m1 = mn1;

        float rs0 = 0.f, rs1 = 0.f;
        #pragma unroll
        for (int ni = 0; ni < 8; ni++) {
            s[ni][0] = __expf(s[ni][0] - mn0);
            s[ni][1] = __expf(s[ni][1] - mn0);
            s[ni][2] = __expf(s[ni][2] - mn1);
            s[ni][3] = __expf(s[ni][3] - mn1);
            rs0 += s[ni][0] + s[ni][1];
            rs1 += s[ni][2] + s[ni][3];
        }
        rs0 += __shfl_xor_sync(0xffffffffu, rs0, 1);
        rs0 += __shfl_xor_sync(0xffffffffu, rs0, 2);
        rs1 += __shfl_xor_sync(0xffffffffu, rs1, 1);
        rs1 += __shfl_xor_sync(0xffffffffu, rs1, 2);
        l0 = l0 * a0 + rs0;
        l1 = l1 * a1 + rs1;

        #pragma unroll
        for (int ni = 0; ni < 8; ni++) {
            o[ni][0] *= a0; o[ni][1] *= a0;
            o[ni][2] *= a1; o[ni][3] *= a1;
        }

        // ---- P -> smem (tf32), A-fragment layout
        #pragma unroll
        for (int ni = 0; ni < 8; ni++) {
            uint2 w0 = make_uint2(f2tf(s[ni][0]), f2tf(s[ni][1]));
            uint2 w1 = make_uint2(f2tf(s[ni][2]), f2tf(s[ni][3]));
            *(uint2*)&Pq[(wq + g    ) * QST + ni * 8 + 2 * t] = w0;
            *(uint2*)&Pq[(wq + g + 8) * QST + ni * 8 + 2 * t] = w1;
        }
        __syncwarp();

        // ---- O += P @ V
        #pragma unroll
        for (int ks = 0; ks < 8; ks++) {
            uint32_t a[4];
            a[0] = Pq[(wq + g    ) * QST + ks * 8 + t];
            a[1] = Pq[(wq + g + 8) * QST + ks * 8 + t];
            a[2] = Pq[(wq + g    ) * QST + ks * 8 + t + 4];
            a[3] = Pq[(wq + g + 8) * QST + ks * 8 + t + 4];
            #pragma unroll
            for (int ni = 0; ni < 8; ni++) {
                uint32_t b0 = Vsb[(ks * 8 + t    ) * VST + ni * 8 + g];
                uint32_t b1 = Vsb[(ks * 8 + t + 4) * VST + ni * 8 + g];
                mma_tf32(o[ni], a, b0, b1);
            }
        }
        __syncthreads();
    }

    // ---- epilogue
    float inv0 = 1.f / l0, inv1 = 1.f / l1;
    const int qg0 = q0 + wq + g, qg1 = qg0 + 8;
    #pragma unroll
    for (int ni = 0; ni < 8; ni++) {
        int c = h * HD + ni * 8 + 2 * t;
        *(float2*)&ctx[(size_t)(b * SEQ + qg0) * DOUT + c] =
            make_float2(o[ni][0] * inv0, o[ni][1] * inv0);
        *(float2*)&ctx[(size_t)(b * SEQ + qg1) * DOUT + c] =
            make_float2(o[ni][2] * inv1, o[ni][3] * inv1);
    }
}

// ------------------------------- launcher -------------------------------------
extern "C" void kernel_launch(void* const* d_in, const int* in_sizes, int n_in,
                              void* d_out, int out_size)
{
    const float* x    = (const float*)d_in[0];
    const float* Wq   = (const float*)d_in[1];
    const float* Wk   = (const float*)d_in[2];
    const float* Wv   = (const float*)d_in[3];
    const float* Wo   = (const float*)d_in[4];
    const float* cosb = (const float*)d_in[5];
    const float* sinb = (const float*)d_in[6];
    float* out = (float*)d_out;

    float *pQ, *pK, *pV, *pCtx;
    uint32_t *pQr, *pKr, *pVr;
    cudaGetSymbolAddress((void**)&pQ,   g_Q);
    cudaGetSymbolAddress((void**)&pK,   g_K);
    cudaGetSymbolAddress((void**)&pV,   g_V);
    cudaGetSymbolAddress((void**)&pQr,  g_Qr);
    cudaGetSymbolAddress((void**)&pKr,  g_Kr);
    cudaGetSymbolAddress((void**)&pVr,  g_Vr);
    cudaGetSymbolAddress((void**)&pCtx, g_ctx);

    dim3 thr(256);

    cudaFuncSetAttribute(sgemm_tc, cudaFuncAttributeMaxDynamicSharedMemorySize, SGEMM_SMEM);
    cudaFuncSetAttribute(attn_tc,  cudaFuncAttributeMaxDynamicSharedMemorySize, ATTN_SMEM);

    // QKV projections
    sgemm_tc<<<dim3(DOUT/128, ROWS/128), thr, SGEMM_SMEM>>>(x, Wq, pQ, ROWS, DOUT, DIN);
    sgemm_tc<<<dim3(DKV /128, ROWS/128), thr, SGEMM_SMEM>>>(x, Wk, pK, ROWS, DKV, DIN);
    sgemm_tc<<<dim3(DKV /128, ROWS/128), thr, SGEMM_SMEM>>>(x, Wv, pV, ROWS, DKV, DIN);

    // RoPE + head-major transposes + tf32 preconvert
    rope_k<NH, 5><<<(ROWS * NH  * 32) / 256, thr>>>(pQ, cosb, sinb, pQr);
    rope_k<NKV, 3><<<(ROWS * NKV * 32) / 256, thr>>>(pK, cosb, sinb, pKr);
    vtrans_k<<<(ROWS * DKV) / 256, thr>>>(pV, pVr);

    // causal flash attention (tf32 tensor core, double-buffered)
    attn_tc<<<dim3(SEQ/128, BATCH*NH), thr, ATTN_SMEM>>>(pQr, pKr, pVr, pCtx);

    // output projection
    sgemm_tc<<<dim3(DOUT/128, ROWS/128), thr, SGEMM_SMEM>>>(pCtx, Wo, out, ROWS, DOUT, DIN);
}

// round 5
// speedup vs baseline: 3.3132x; 1.0116x over previous
#include <cuda_runtime.h>
#include <math.h>
#include <stdint.h>

#define BATCH 2
#define SEQ   2048
#define DIN   2048
#define DOUT  2048
#define NH    32
#define NKV   8
#define HD    64
#define ROWS  (BATCH*SEQ)    /* 4096 */
#define DKV   (NKV*HD)       /* 512  */

// ---------------- scratch (static device arrays; no allocation) ----------------
__device__ uint32_t g_Qr [ROWS*DOUT];   // [B,NH,S,HD]  tf32
__device__ uint32_t g_Kr [ROWS*DKV];    // [B,NKV,S,HD] tf32
__device__ uint32_t g_Vr [ROWS*DKV];    // [B,NKV,S,HD] tf32
__device__ float    g_ctx[ROWS*DOUT];   // [B*S, NH*HD]

__device__ __forceinline__ uint32_t f2tf(float f) {
    uint32_t r;
    asm("cvt.rna.tf32.f32 %0, %1;" : "=r"(r) : "f"(f));
    return r;
}

__device__ __forceinline__ void mma_tf32(float* c, const uint32_t* a,
                                         uint32_t b0, uint32_t b1) {
    asm volatile(
        "mma.sync.aligned.m16n8k8.row.col.f32.tf32.tf32.f32 "
        "{%0,%1,%2,%3}, {%4,%5,%6,%7}, {%8,%9}, {%0,%1,%2,%3};"
        : "+f"(c[0]), "+f"(c[1]), "+f"(c[2]), "+f"(c[3])
        : "r"(a[0]), "r"(a[1]), "r"(a[2]), "r"(a[3]), "r"(b0), "r"(b1));
}

__device__ __forceinline__ void cp16(uint32_t smem_byte, const void* g) {
    asm volatile("cp.async.cg.shared.global [%0], [%1], 16;\n"
                 :: "r"(smem_byte), "l"(g));
}
__device__ __forceinline__ void cp_commit() {
    asm volatile("cp.async.commit_group;\n" ::);
}
template <int N>
__device__ __forceinline__ void cp_wait() {
    asm volatile("cp.async.wait_group %0;\n" :: "n"(N));
}

// smem strides (both conflict-free for their access patterns)
#define AST 36
#define BST 136
#define SGEMM_SMEM ((2*128*AST + 2*32*BST) * 4)   /* 71680 bytes */

// ================= fused QKV projection + RoPE + transpose + tf32 ==============
// grid (24, 32): bx<16 -> Q (Wq, rope), bx<20 -> K (Wk, rope), else V (Wv).
// Each warp's 64-col tile == one head; rope pair (d, d+32) lives in acc[ni]/acc[ni+4].
__global__ __launch_bounds__(256) void qkv_tc(
    const float* __restrict__ x,
    const float* __restrict__ Wq, const float* __restrict__ Wk,
    const float* __restrict__ Wv,
    const float* __restrict__ cosb, const float* __restrict__ sinb,
    uint32_t* __restrict__ Qr, uint32_t* __restrict__ Kr,
    uint32_t* __restrict__ Vr)
{
    extern __shared__ float smf[];
    float* As = smf;                    // [2][128][36]
    float* Bs = smf + 2 * 128 * AST;    // [2][32][136]

    const int bx = blockIdx.x;
    const float* W; uint32_t* outp; int N, col0, nh; bool dorope;
    if (bx < 16)      { W = Wq; outp = Qr; N = DOUT; col0 = bx * 128;        nh = NH;  dorope = true;  }
    else if (bx < 20) { W = Wk; outp = Kr; N = DKV;  col0 = (bx - 16) * 128; nh = NKV; dorope = true;  }
    else              { W = Wv; outp = Vr; N = DKV;  col0 = (bx - 20) * 128; nh = NKV; dorope = false; }

    const int tid  = threadIdx.x;
    const int warp = tid >> 5, lane = tid & 31;
    const int g    = lane >> 2, t = lane & 3;
    const int wm   = (warp & 3) * 32;
    const int wn   = (warp >> 2) * 64;
    const int row0 = blockIdx.y * 128;

    const uint32_t sA = (uint32_t)__cvta_generic_to_shared(As);
    const uint32_t sB = (uint32_t)__cvta_generic_to_shared(Bs);

    const int a_c = (tid & 7) * 4,  a_r = tid >> 3;
    const int b_c = (tid & 31) * 4, b_r = tid >> 5;

    auto LOAD = [&](int k0, int buf) {
        const float* ap = x + (size_t)(row0 + a_r) * DIN + k0 + a_c;
        uint32_t da = sA + (uint32_t)(buf * 128 * AST + a_r * AST + a_c) * 4;
        #pragma unroll
        for (int i = 0; i < 4; i++)
            cp16(da + i * 32 * AST * 4, ap + (size_t)i * 32 * DIN);
        const float* bp = W + (size_t)(k0 + b_r) * N + col0 + b_c;
        uint32_t db = sB + (uint32_t)(buf * 32 * BST + b_r * BST + b_c) * 4;
        #pragma unroll
        for (int i = 0; i < 4; i++)
            cp16(db + i * 8 * BST * 4, bp + (size_t)i * 8 * N);
    };

    float acc[2][8][4];
    #pragma unroll
    for (int mi = 0; mi < 2; mi++)
        #pragma unroll
        for (int ni = 0; ni < 8; ni++)
            #pragma unroll
            for (int r = 0; r < 4; r++) acc[mi][ni][r] = 0.f;

    LOAD(0, 0);
    cp_commit();

    const int niter = DIN / 32;
    for (int it = 0; it < niter; it++) {
        const int buf = it & 1;
        if (it + 1 < niter) {
            LOAD((it + 1) * 32, buf ^ 1);
            cp_commit();
            cp_wait<1>();
        } else {
            cp_wait<0>();
        }
        __syncthreads();

        const float* Asb = As + buf * 128 * AST;
        const float* Bsb = Bs + buf * 32 * BST;
        #pragma unroll
        for (int ks = 0; ks < 4; ks++) {
            const int kb = ks * 8;
            uint32_t a[2][4], b[8][2];
            #pragma unroll
            for (int mi = 0; mi < 2; mi++) {
                const int m0 = wm + mi * 16 + g;
                a[mi][0] = f2tf(Asb[(m0    ) * AST + kb + t]);
                a[mi][1] = f2tf(Asb[(m0 + 8) * AST + kb + t]);
                a[mi][2] = f2tf(Asb[(m0    ) * AST + kb + t + 4]);
                a[mi][3] = f2tf(Asb[(m0 + 8) * AST + kb + t + 4]);
            }
            #pragma unroll
            for (int ni = 0; ni < 8; ni++) {
                const int n0 = wn + ni * 8 + g;
                b[ni][0] = f2tf(Bsb[(kb + t    ) * BST + n0]);
                b[ni][1] = f2tf(Bsb[(kb + t + 4) * BST + n0]);
            }
            #pragma unroll
            for (int mi = 0; mi < 2; mi++)
                #pragma unroll
                for (int ni = 0; ni < 8; ni++)
                    mma_tf32(acc[mi][ni], a[mi], b[ni][0], b[ni][1]);
        }
        __syncthreads();
    }

    // ---- fused epilogue: (RoPE) + transpose to [b,h,s,d] + tf32 convert
    const int hq = (col0 + wn) >> 6;             // head index
    #pragma unroll
    for (int mi = 0; mi < 2; mi++) {
        const int rbase = row0 + wm + mi * 16 + g;
        #pragma unroll
        for (int v = 0; v < 2; v++) {
            const int r = rbase + v * 8;
            const int b = r >> 11, s = r & 2047;
            uint32_t* op = outp + ((size_t)(b * nh + hq) * SEQ + s) * HD;
            if (dorope) {
                #pragma unroll
                for (int ni = 0; ni < 4; ni++) {
                    const int d = ni * 8 + 2 * t;
                    float x1a = acc[mi][ni    ][v*2], x1b = acc[mi][ni    ][v*2+1];
                    float x2a = acc[mi][ni + 4][v*2], x2b = acc[mi][ni + 4][v*2+1];
                    float2 c1 = *(const float2*)&cosb[s * HD + d];
                    float2 s1 = *(const float2*)&sinb[s * HD + d];
                    float2 c2 = *(const float2*)&cosb[s * HD + d + 32];
                    float2 s2 = *(const float2*)&sinb[s * HD + d + 32];
                    uint2 w1 = make_uint2(f2tf(x1a * c1.x - x2a * s1.x),
                                          f2tf(x1b * c1.y - x2b * s1.y));
                    uint2 w2 = make_uint2(f2tf(x2a * c2.x + x1a * s2.x),
                                          f2tf(x2b * c2.y + x1b * s2.y));
                    *(uint2*)&op[d]      = w1;
                    *(uint2*)&op[d + 32] = w2;
                }
            } else {
                #pragma unroll
                for (int ni = 0; ni < 8; ni++) {
                    const int d = ni * 8 + 2 * t;
                    *(uint2*)&op[d] = make_uint2(f2tf(acc[mi][ni][v*2]),
                                                 f2tf(acc[mi][ni][v*2+1]));
                }
            }
        }
    }
}

// ================= plain tf32 GEMM (output projection) =========================
__global__ __launch_bounds__(256) void sgemm_tc(
    const float* __restrict__ A, const float* __restrict__ B,
    float* __restrict__ C, int M, int N, int K)
{
    extern __shared__ float smf[];
    float* As = smf;
    float* Bs = smf + 2 * 128 * AST;

    const int tid  = threadIdx.x;
    const int warp = tid >> 5, lane = tid & 31;
    const int g    = lane >> 2, t = lane & 3;
    const int wm   = (warp & 3) * 32;
    const int wn   = (warp >> 2) * 64;
    const int row0 = blockIdx.y * 128, col0 = blockIdx.x * 128;

    const uint32_t sA = (uint32_t)__cvta_generic_to_shared(As);
    const uint32_t sB = (uint32_t)__cvta_generic_to_shared(Bs);

    const int a_c = (tid & 7) * 4,  a_r = tid >> 3;
    const int b_c = (tid & 31) * 4, b_r = tid >> 5;

    auto LOAD = [&](int k0, int buf) {
        const float* ap = A + (size_t)(row0 + a_r) * K + k0 + a_c;
        uint32_t da = sA + (uint32_t)(buf * 128 * AST + a_r * AST + a_c) * 4;
        #pragma unroll
        for (int i = 0; i < 4; i++)
            cp16(da + i * 32 * AST * 4, ap + (size_t)i * 32 * K);
        const float* bp = B + (size_t)(k0 + b_r) * N + col0 + b_c;
        uint32_t db = sB + (uint32_t)(buf * 32 * BST + b_r * BST + b_c) * 4;
        #pragma unroll
        for (int i = 0; i < 4; i++)
            cp16(db + i * 8 * BST * 4, bp + (size_t)i * 8 * N);
    };

    float acc[2][8][4];
    #pragma unroll
    for (int mi = 0; mi < 2; mi++)
        #pragma unroll
        for (int ni = 0; ni < 8; ni++)
            #pragma unroll
            for (int r = 0; r < 4; r++) acc[mi][ni][r] = 0.f;

    LOAD(0, 0);
    cp_commit();

    const int niter = K / 32;
    for (int it = 0; it < niter; it++) {
        const int buf = it & 1;
        if (it + 1 < niter) {
            LOAD((it + 1) * 32, buf ^ 1);
            cp_commit();
            cp_wait<1>();
        } else {
            cp_wait<0>();
        }
        __syncthreads();

        const float* Asb = As + buf * 128 * AST;
        const float* Bsb = Bs + buf * 32 * BST;
        #pragma unroll
        for (int ks = 0; ks < 4; ks++) {
            const int kb = ks * 8;
            uint32_t a[2][4], b[8][2];
            #pragma unroll
            for (int mi = 0; mi < 2; mi++) {
                const int m0 = wm + mi * 16 + g;
                a[mi][0] = f2tf(Asb[(m0    ) * AST + kb + t]);
                a[mi][1] = f2tf(Asb[(m0 + 8) * AST + kb + t]);
                a[mi][2] = f2tf(Asb[(m0    ) * AST + kb + t + 4]);
                a[mi][3] = f2tf(Asb[(m0 + 8) * AST + kb + t + 4]);
            }
            #pragma unroll
            for (int ni = 0; ni < 8; ni++) {
                const int n0 = wn + ni * 8 + g;
                b[ni][0] = f2tf(Bsb[(kb + t    ) * BST + n0]);
                b[ni][1] = f2tf(Bsb[(kb + t + 4) * BST + n0]);
            }
            #pragma unroll
            for (int mi = 0; mi < 2; mi++)
                #pragma unroll
                for (int ni = 0; ni < 8; ni++)
                    mma_tf32(acc[mi][ni], a[mi], b[ni][0], b[ni][1]);
        }
        __syncthreads();
    }

    #pragma unroll
    for (int mi = 0; mi < 2; mi++)
        #pragma unroll
        for (int ni = 0; ni < 8; ni++) {
            const int r = row0 + wm + mi * 16 + g;
            const int c = col0 + wn + ni * 8 + t * 2;
            *(float2*)(C + (size_t)r * N + c) =
                make_float2(acc[mi][ni][0], acc[mi][ni][1]);
            *(float2*)(C + (size_t)(r + 8) * N + c) =
                make_float2(acc[mi][ni][2], acc[mi][ni][3]);
        }
}

// ================= tf32 flash attention (unchanged from R4) ====================
#define QST 68
#define VST 72
#define ATTN_SMEM ((128*QST + 2*64*QST + 2*64*VST) * 4)   /* 106496 bytes */

__global__ __launch_bounds__(256) void attn_tc(
    const uint32_t* __restrict__ Qr, const uint32_t* __restrict__ Kr,
    const uint32_t* __restrict__ Vr, float* __restrict__ ctx)
{
    extern __shared__ uint32_t smu[];
    uint32_t* Pq = smu;                   // [128][68]
    uint32_t* Ks = smu + 128 * QST;       // [2][64][68]
    uint32_t* Vs = Ks  + 2 * 64 * QST;    // [2][64][72]

    const int bh = blockIdx.y;
    const int b = bh >> 5, h = bh & 31, g2 = h >> 2;
    const int qt = gridDim.x - 1 - blockIdx.x;
    const int q0 = qt * 128;
    const int tid = threadIdx.x;
    const int warp = tid >> 5, lane = tid & 31;
    const int g = lane >> 2, t = lane & 3;
    const int wq = warp * 16;

    const uint32_t* Qbase = Qr + ((size_t)bh * SEQ + q0) * HD;
    const uint32_t* Kbase = Kr + (size_t)(b * NKV + g2) * SEQ * HD;
    const uint32_t* Vbase = Vr + (size_t)(b * NKV + g2) * SEQ * HD;

    const uint32_t sK = (uint32_t)__cvta_generic_to_shared(Ks);
    const uint32_t sV = (uint32_t)__cvta_generic_to_shared(Vs);

    const int kc = (tid & 15) * 4, kr = tid >> 4;

    auto LOADKV = [&](int k0, int buf) {
        const uint32_t* kp = Kbase + (size_t)(k0 + kr) * HD + kc;
        const uint32_t* vp = Vbase + (size_t)(k0 + kr) * HD + kc;
        uint32_t dk = sK + (uint32_t)(buf * 64 * QST + kr * QST + kc) * 4;
        uint32_t dv = sV + (uint32_t)(buf * 64 * VST + kr * VST + kc) * 4;
        #pragma unroll
        for (int i = 0; i < 4; i++) {
            cp16(dk + i * 16 * QST * 4, kp + (size_t)i * 16 * HD);
            cp16(dv + i * 16 * VST * 4, vp + (size_t)i * 16 * HD);
        }
    };

    LOADKV(0, 0);
    cp_commit();
    #pragma unroll
    for (int i = 0; i < 8; i++) {
        int idx = i * 256 + tid;
        int r = idx >> 4, c = (idx & 15) * 4;
        *(uint4*)&Pq[r * QST + c] = *(const uint4*)&Qbase[r * HD + c];
    }
    __syncthreads();

    uint32_t qf[8][4];
    #pragma unroll
    for (int s = 0; s < 8; s++) {
        qf[s][0] = Pq[(wq + g    ) * QST + s * 8 + t];
        qf[s][1] = Pq[(wq + g + 8) * QST + s * 8 + t];
        qf[s][2] = Pq[(wq + g    ) * QST + s * 8 + t + 4];
        qf[s][3] = Pq[(wq + g + 8) * QST + s * 8 + t + 4];
    }

    float o[8][4];
    #pragma unroll
    for (int ni = 0; ni < 8; ni++)
        #pragma unroll
        for (int r = 0; r < 4; r++) o[ni][r] = 0.f;
    float m0 = -1e30f, m1 = -1e30f, l0 = 0.f, l1 = 0.f;

    const int ntiles = qt * 2 + 2;
    for (int tt = 0; tt < ntiles; tt++) {
        const int buf = tt & 1;
        if (tt + 1 < ntiles) {
            LOADKV((tt + 1) * 64, buf ^ 1);
            cp_commit();
            cp_wait<1>();
        } else {
            cp_wait<0>();
        }
        __syncthreads();

        const uint32_t* Ksb = Ks + buf * 64 * QST;
        const uint32_t* Vsb = Vs + buf * 64 * VST;
        const int k0 = tt * 64;

        float s[8][4];
        #pragma unroll
        for (int ni = 0; ni < 8; ni++)
            #pragma unroll
            for (int r = 0; r < 4; r++) s[ni][r] = 0.f;

        #pragma unroll
        for (int ds = 0; ds < 8; ds++) {
            #pragma unroll
            for (int ni = 0; ni < 8; ni++) {
                uint32_t b0 = Ksb[(ni * 8 + g) * QST + ds * 8 + t];
                uint32_t b1 = Ksb[(ni * 8 + g) * QST + ds * 8 + t + 4];
                mma_tf32(s[ni], qf[ds], b0, b1);
            }
        }

        const bool do_mask = (k0 + 63 > q0);
        const int qg0 = q0 + wq + g, qg1 = qg0 + 8;
        #pragma unroll
        for (int ni = 0; ni < 8; ni++) {
            #pragma unroll
            for (int r = 0; r < 4; r++) {
                float v = s[ni][r] * 0.125f;
                if (do_mask) {
                    int kg = k0 + ni * 8 + 2 * t + (r & 1);
                    int qg = (r >= 2) ? qg1 : qg0;
                    if (kg > qg) v = -1e30f;
                }
                s[ni][r] = v;
            }
        }

        float tm0 = -1e30f, tm1 = -1e30f;
        #pragma unroll
        for (int ni = 0; ni < 8; ni++) {
            tm0 = fmaxf(tm0, fmaxf(s[ni][0], s[ni][1]));
            tm1 = fmaxf(tm1, fmaxf(s[ni][2], s[ni][3]));
        }
        tm0 = fmaxf(tm0, __shfl_xor_sync(0xffffffffu, tm0, 1));
        tm0 = fmaxf(tm0, __shfl_xor_sync(0xffffffffu, tm0, 2));
        tm1 = fmaxf(tm1, __shfl_xor_sync(0xffffffffu, tm1, 1));
        tm1 = fmaxf(tm1, __shfl_xor_sync(0xffffffffu, tm1, 2));

        float mn0 = fmaxf(m0, tm0), mn1 = fmaxf(m1, tm1);
        float a0 = __expf(m0 - mn0), a1 = __expf(m1 - mn1);
        m0 = mn0; m1 = mn1;

        float rs0 = 0.f, rs1 = 0.f;
        #pragma unroll
        for (int ni = 0; ni < 8; ni++) {
            s[ni][0] = __expf(s[ni][0] - mn0);
            s[ni][1] = __expf(s[ni][1] - mn0);
            s[ni][2] = __expf(s[ni][2] - mn1);
            s[ni][3] = __expf(s[ni][3] - mn1);
            rs0 += s[ni][0] + s[ni][1];
            rs1 += s[ni][2] + s[ni][3];
        }
        rs0 += __shfl_xor_sync(0xffffffffu, rs0, 1);
        rs0 += __shfl_xor_sync(0xffffffffu, rs0, 2);
        rs1 += __shfl_xor_sync(0xffffffffu, rs1, 1);
        rs1 += __shfl_xor_sync(0xffffffffu, rs1, 2);
        l0 = l0 * a0 + rs0;
        l1 = l1 * a1 + rs1;

        #pragma unroll
        for (int ni = 0; ni < 8; ni++) {
            o[ni][0] *= a0; o[ni][1] *= a0;
            o[ni][2] *= a1; o[ni][3] *= a1;
        }

        #pragma unroll
        for (int ni = 0; ni < 8; ni++) {
            uint2 w0 = make_uint2(f2tf(s[ni][0]), f2tf(s[ni][1]));
            uint2 w1 = make_uint2(f2tf(s[ni][2]), f2tf(s[ni][3]));
            *(uint2*)&Pq[(wq + g    ) * QST + ni * 8 + 2 * t] = w0;
            *(uint2*)&Pq[(wq + g + 8) * QST + ni * 8 + 2 * t] = w1;
        }
        __syncwarp();

        #pragma unroll
        for (int ks = 0; ks < 8; ks++) {
            uint32_t a[4];
            a[0] = Pq[(wq + g    ) * QST + ks * 8 + t];
            a[1] = Pq[(wq + g + 8) * QST + ks * 8 + t];
            a[2] = Pq[(wq + g    ) * QST + ks * 8 + t + 4];
            a[3] = Pq[(wq + g + 8) * QST + ks * 8 + t + 4];
            #pragma unroll
            for (int ni = 0; ni < 8; ni++) {
                uint32_t b0 = Vsb[(ks * 8 + t    ) * VST + ni * 8 + g];
                uint32_t b1 = Vsb[(ks * 8 + t + 4) * VST + ni * 8 + g];
                mma_tf32(o[ni], a, b0, b1);
            }
        }
        __syncthreads();
    }

    float inv0 = 1.f / l0, inv1 = 1.f / l1;
    const int qg0 = q0 + wq + g, qg1 = qg0 + 8;
    #pragma unroll
    for (int ni = 0; ni < 8; ni++) {
        int c = h * HD + ni * 8 + 2 * t;
        *(float2*)&ctx[(size_t)(b * SEQ + qg0) * DOUT + c] =
            make_float2(o[ni][0] * inv0, o[ni][1] * inv0);
        *(float2*)&ctx[(size_t)(b * SEQ + qg1) * DOUT + c] =
            make_float2(o[ni][2] * inv1, o[ni][3] * inv1);
    }
}

// ------------------------------- launcher -------------------------------------
extern "C" void kernel_launch(void* const* d_in, const int* in_sizes, int n_in,
                              void* d_out, int out_size)
{
    const float* x    = (const float*)d_in[0];
    const float* Wq   = (const float*)d_in[1];
    const float* Wk   = (const float*)d_in[2];
    const float* Wv   = (const float*)d_in[3];
    const float* Wo   = (const float*)d_in[4];
    const float* cosb = (const float*)d_in[5];
    const float* sinb = (const float*)d_in[6];
    float* out = (float*)d_out;

    float *pCtx;
    uint32_t *pQr, *pKr, *pVr;
    cudaGetSymbolAddress((void**)&pQr,  g_Qr);
    cudaGetSymbolAddress((void**)&pKr,  g_Kr);
    cudaGetSymbolAddress((void**)&pVr,  g_Vr);
    cudaGetSymbolAddress((void**)&pCtx, g_ctx);

    dim3 thr(256);

    cudaFuncSetAttribute(qkv_tc,   cudaFuncAttributeMaxDynamicSharedMemorySize, SGEMM_SMEM);
    cudaFuncSetAttribute(sgemm_tc, cudaFuncAttributeMaxDynamicSharedMemorySize, SGEMM_SMEM);
    cudaFuncSetAttribute(attn_tc,  cudaFuncAttributeMaxDynamicSharedMemorySize, ATTN_SMEM);

    // fused QKV projection + RoPE + head-transpose + tf32 convert
    qkv_tc<<<dim3(24, ROWS/128), thr, SGEMM_SMEM>>>(
        x, Wq, Wk, Wv, cosb, sinb, pQr, pKr, pVr);

    // causal flash attention (tf32 tensor core, double-buffered)
    attn_tc<<<dim3(SEQ/128, BATCH*NH), thr, ATTN_SMEM>>>(pQr, pKr, pVr, pCtx);

    // output projection
    sgemm_tc<<<dim3(DOUT/128, ROWS/128), thr, SGEMM_SMEM>>>(pCtx, Wo, out, ROWS, DOUT, DIN);
}